// round 16
// baseline (speedup 1.0000x reference)
#include <cuda_runtime.h>

#define BB     4
#define NN     8192
#define TPB    128
#define YSPLIT 16                   // blockIdx.y groups
#define TPG    2                    // gt tiles per block (sequential)
#define CHUNK  256                  // gt points per tile
#define QPT    8                    // query points per thread (4 packed pairs)
#define XT     (NN / (TPB * QPT))   // 8 query tiles
#define NWARP  (TPB / 32)
#define JT     4                    // columns per iteration (butterfly ILP)
#define NCLS   4                    // lane classes kept after truncated butterfly

// dir0 partials: min over the block's 512 gt pts, per (b, ygroup, query) -> 2MB
__device__ float g_part0[BB * YSPLIT * NN];
// dir1 partials: min over the block's 1024 queries, per (b, qtile, gt)   -> 1MB
__device__ float g_part1[BB * XT * NN];

typedef unsigned long long ull;

__device__ __forceinline__ ull fma2(ull a, ull b, ull c) {
    ull d;
    asm("fma.rn.f32x2 %0, %1, %2, %3;" : "=l"(d) : "l"(a), "l"(b), "l"(c));
    return d;
}
__device__ __forceinline__ ull add2(ull a, ull b) {
    ull d;
    asm("add.rn.f32x2 %0, %1, %2;" : "=l"(d) : "l"(a), "l"(b));
    return d;
}
// Pure bit-cast pack/unpack: register-pair aliasing, no MOVs.
__device__ __forceinline__ ull pack2(float lo, float hi) {
    return __double_as_longlong(
        __hiloint2double(__float_as_int(hi), __float_as_int(lo)));
}
__device__ __forceinline__ void unpack2(ull v, float& lo, float& hi) {
    const double d = __longlong_as_double(v);
    lo = __int_as_float(__double2loint(d));
    hi = __int_as_float(__double2hiint(d));
}

// Fused both-direction kernel (R12-validated hot loop, at the fp32 roofline):
//   v1 = (gg - 2 p.g) + pp   (3 FFMA2 + 1 ADD2 per packed query pair)
//   dir0 row-min on v1 (min_j(v0)+pp == min_j(v1)); dir1 col-min via
//   truncated 3-stage butterfly. Each block sweeps TPG=2 gt tiles.
__global__ __launch_bounds__(TPB, 7) void chamfer_fused_kernel(
    const float* __restrict__ pred, const float* __restrict__ gt,
    float* __restrict__ out) {
    // Duplicated gt layout for packed math (32B/point):
    //   sq[2j]   = {-2gx, -2gx, -2gy, -2gy}
    //   sq[2j+1] = {-2gz, -2gz, |g|^2, |g|^2}
    __shared__ float4 sq[2 * CHUNK];                  // 8KB
    __shared__ float  colmin[NWARP][NCLS][CHUNK];     // 16KB

    const int tid  = threadIdx.x;
    const int wid  = tid >> 5;
    const int lane = tid & 31;
    const int b    = blockIdx.z;

    // Zero the scalar output once, before the reduce kernel's atomics.
    if (b == 0 && blockIdx.x == 0 && blockIdx.y == 0 && tid == 0)
        out[0] = 0.0f;

    const float* Pb = pred + (size_t)b * NN * 3;
    const float* Gb = gt   + (size_t)b * NN * 3;

    // --- each thread owns QPT=8 queries, as 4 packed f32x2 pairs ---
    const int base = (blockIdx.x * TPB + tid) * QPT;

    ull pxx[QPT / 2], pyy[QPT / 2], pzz[QPT / 2], pp01[QPT / 2];
#pragma unroll
    for (int p = 0; p < QPT / 2; p++) {
        const int   q0 = base + 2 * p, q1 = q0 + 1;
        const float ax = Pb[q0 * 3 + 0], ay = Pb[q0 * 3 + 1], az = Pb[q0 * 3 + 2];
        const float bx = Pb[q1 * 3 + 0], by = Pb[q1 * 3 + 1], bz = Pb[q1 * 3 + 2];
        pxx[p]  = pack2(ax, bx);
        pyy[p]  = pack2(ay, by);
        pzz[p]  = pack2(az, bz);
        pp01[p] = pack2(ax * ax + ay * ay + az * az,
                        bx * bx + by * by + bz * bz);
    }

    float mn[QPT];
#pragma unroll
    for (int q = 0; q < QPT; q++) mn[q] = 3.4e38f;

    const ulonglong2* __restrict__ s2 = reinterpret_cast<const ulonglong2*>(sq);

    for (int t = 0; t < TPG; t++) {
        // --- cooperative load + transform + duplicate of this gt tile ---
        const int coff = (blockIdx.y * TPG + t) * CHUNK;
        for (int i = tid; i < CHUNK; i += TPB) {
            const float gx = Gb[(coff + i) * 3 + 0];
            const float gy = Gb[(coff + i) * 3 + 1];
            const float gz = Gb[(coff + i) * 3 + 2];
            const float gg = gx * gx + gy * gy + gz * gz;
            sq[2 * i]     = make_float4(-2.0f * gx, -2.0f * gx,
                                        -2.0f * gy, -2.0f * gy);
            sq[2 * i + 1] = make_float4(-2.0f * gz, -2.0f * gz, gg, gg);
        }
        __syncthreads();

        for (int j0 = 0; j0 < CHUNK; j0 += JT) {
            float m4[JT];
            // --- compute phase: JT columns ---
#pragma unroll
            for (int c = 0; c < JT; c++) {
                const int        j = j0 + c;
                const ulonglong2 a = s2[2 * j];      // {-2gx,-2gx, -2gy,-2gy}
                const ulonglong2 w = s2[2 * j + 1];  // {-2gz,-2gz,  gg,  gg }
                float tq[QPT];
#pragma unroll
                for (int p = 0; p < QPT / 2; p++) {
                    const ull s = fma2(pxx[p], a.x,
                                       fma2(pyy[p], a.y,
                                            fma2(pzz[p], w.x, w.y)));
                    const ull v = add2(s, pp01[p]);   // full distance v1
                    float lo, hi;
                    unpack2(v, lo, hi);
                    mn[2 * p]     = fminf(mn[2 * p], lo);   // dir0 on v1
                    mn[2 * p + 1] = fminf(mn[2 * p + 1], hi);
                    tq[2 * p] = lo;
                    tq[2 * p + 1] = hi;
                }
                m4[c] = fminf(fminf(fminf(tq[0], tq[1]), fminf(tq[2], tq[3])),
                              fminf(fminf(tq[4], tq[5]), fminf(tq[6], tq[7])));
            }
            // --- truncated butterfly: 3 interleaved stages (xor 16, 8, 4) ---
#pragma unroll
            for (int st = 16; st >= 4; st >>= 1) {
#pragma unroll
                for (int c = 0; c < JT; c++)
                    m4[c] = fminf(m4[c],
                                  __shfl_xor_sync(0xffffffffu, m4[c], st));
            }
            // lanes 0-3 store their class row for these 4 columns (STS.128)
            if (lane < NCLS)
                *reinterpret_cast<float4*>(&colmin[wid][lane][j0]) =
                    make_float4(m4[0], m4[1], m4[2], m4[3]);
        }
        __syncthreads();

        // dir1 epilogue for this tile: combine NWARP x NCLS mins per column
        for (int j = tid; j < CHUNK; j += TPB) {
            float m = colmin[0][0][j];
#pragma unroll
            for (int w = 0; w < NWARP; w++)
#pragma unroll
                for (int c = 0; c < NCLS; c++)
                    m = fminf(m, colmin[w][c][j]);
            g_part1[((size_t)(b * XT + blockIdx.x)) * NN + coff + j] = m;
        }
        // No extra sync needed: next iteration's sq/colmin writes happen
        // after the __syncthreads() that follows the tile load.
    }

    // dir0 partials out (full distances over this block's 512 gt points)
    const size_t o0 = ((size_t)(b * YSPLIT + blockIdx.y)) * NN + base;
#pragma unroll
    for (int q = 0; q < QPT; q++) g_part0[o0 + q] = mn[q];
}

// Final reduce: dir0 = min over ygroups ; dir1 = min over query tiles.
// result = sum(all dists) / (B*N)   (N == M, forward_weight = 1)
#define TPB_RED 256
__global__ __launch_bounds__(TPB_RED) void chamfer_reduce_kernel(
    float* __restrict__ out) {
    __shared__ float red[TPB_RED];

    const int tid  = threadIdx.x;
    const int gidx = blockIdx.x * TPB_RED + tid;     // 0 .. 2*B*N-1

    float val;
    if (gidx < BB * NN) {                        // dir0 (pred -> gt)
        const int b = gidx / NN, q = gidx % NN;
        float m = 3.4e38f;
#pragma unroll
        for (int c = 0; c < YSPLIT; c++)
            m = fminf(m, g_part0[((size_t)(b * YSPLIT + c)) * NN + q]);
        val = m;
    } else {                                     // dir1 (gt -> pred)
        const int r = gidx - BB * NN;
        const int b = r / NN, j = r % NN;
        float m = 3.4e38f;
#pragma unroll
        for (int x = 0; x < XT; x++)
            m = fminf(m, g_part1[((size_t)(b * XT + x)) * NN + j]);
        val = m;
    }

    red[tid] = val;
    __syncthreads();
#pragma unroll
    for (int s = TPB_RED / 2; s > 0; s >>= 1) {
        if (tid < s) red[tid] += red[tid + s];
        __syncthreads();
    }
    if (tid == 0)
        atomicAdd(out, red[0] * (1.0f / ((float)BB * (float)NN)));
}

extern "C" void kernel_launch(void* const* d_in, const int* in_sizes, int n_in,
                              void* d_out, int out_size) {
    const float* pred = (const float*)d_in[0];
    const float* gt   = (const float*)d_in[1];
    float*       out  = (float*)d_out;

    dim3 grid(XT, YSPLIT, BB);   // 8 x 16 x 4 = 1024 blocks, single wave
    chamfer_fused_kernel<<<grid, TPB>>>(pred, gt, out);

    chamfer_reduce_kernel<<<(2 * BB * NN) / TPB_RED, TPB_RED>>>(out);
}

// round 17
// speedup vs baseline: 1.1099x; 1.1099x over previous
#include <cuda_runtime.h>

#define BB     4
#define NN     8192
#define TPB    128
#define GSPLIT 32
#define CHUNK  (NN / GSPLIT)        // 256 gt points per block
#define QPT    8                    // query points per thread (4 packed pairs)
#define XT     (NN / (TPB * QPT))   // 8 query tiles
#define NWARP  (TPB / 32)
#define JT     4                    // columns per iteration (butterfly ILP)
#define NCLS   4                    // lane classes kept after truncated butterfly

// dir0 partials: min_j(v1) per (b, chunk, query)  -> 4MB  (full distances)
__device__ float g_part0[BB * GSPLIT * NN];
// dir1 partials: min_i(v1) per (b, query-tile, gt) -> 1MB
__device__ float g_part1[BB * XT * NN];

typedef unsigned long long ull;

__device__ __forceinline__ ull fma2(ull a, ull b, ull c) {
    ull d;
    asm("fma.rn.f32x2 %0, %1, %2, %3;" : "=l"(d) : "l"(a), "l"(b), "l"(c));
    return d;
}
__device__ __forceinline__ ull add2(ull a, ull b) {
    ull d;
    asm("add.rn.f32x2 %0, %1, %2;" : "=l"(d) : "l"(a), "l"(b));
    return d;
}
// Pure bit-cast pack/unpack: register-pair aliasing, no MOVs.
__device__ __forceinline__ ull pack2(float lo, float hi) {
    return __double_as_longlong(
        __hiloint2double(__float_as_int(hi), __float_as_int(lo)));
}
__device__ __forceinline__ void unpack2(ull v, float& lo, float& hi) {
    const double d = __longlong_as_double(v);
    lo = __int_as_float(__double2loint(d));
    hi = __int_as_float(__double2hiint(d));
}

// Fused both-direction kernel (R12 champion structure):
//   v1 = (gg - 2 p.g) + pp   (3 FFMA2 + 1 ADD2 per packed query pair)
// dir0 row-min on v1 (min_j(v0)+pp == min_j(v1), pp const over j).
// dir1 col-min: in-thread tree + truncated 3-stage butterfly (xor 16,8,4),
// lanes 0-3 store their lane-class partials, block epilogue finishes.
__global__ __launch_bounds__(TPB, 7) void chamfer_fused_kernel(
    const float* __restrict__ pred, const float* __restrict__ gt,
    float* __restrict__ out) {
    // Duplicated gt layout for packed math (32B/point):
    //   sq[2j]   = {-2gx, -2gx, -2gy, -2gy}
    //   sq[2j+1] = {-2gz, -2gz, |g|^2, |g|^2}
    __shared__ float4 sq[2 * CHUNK];                  // 8KB
    __shared__ float  colmin[NWARP][NCLS][CHUNK];     // 16KB

    const int tid  = threadIdx.x;
    const int wid  = tid >> 5;
    const int lane = tid & 31;
    const int b    = blockIdx.z;

    // Zero the scalar output once, before the reduce kernel's atomics.
    if (b == 0 && blockIdx.x == 0 && blockIdx.y == 0 && tid == 0)
        out[0] = 0.0f;

    const float* Pb = pred + (size_t)b * NN * 3;
    const float* Gb = gt   + (size_t)b * NN * 3;

    // --- cooperative load + transform + duplicate of gt chunk ---
    const int coff = blockIdx.y * CHUNK;
    for (int i = tid; i < CHUNK; i += TPB) {
        const float gx = Gb[(coff + i) * 3 + 0];
        const float gy = Gb[(coff + i) * 3 + 1];
        const float gz = Gb[(coff + i) * 3 + 2];
        const float gg = gx * gx + gy * gy + gz * gz;
        sq[2 * i]     = make_float4(-2.0f * gx, -2.0f * gx, -2.0f * gy, -2.0f * gy);
        sq[2 * i + 1] = make_float4(-2.0f * gz, -2.0f * gz, gg, gg);
    }
    __syncthreads();

    // --- each thread owns QPT=8 queries, as 4 packed f32x2 pairs ---
    const int base = (blockIdx.x * TPB + tid) * QPT;

    ull pxx[QPT / 2], pyy[QPT / 2], pzz[QPT / 2], pp01[QPT / 2];
#pragma unroll
    for (int p = 0; p < QPT / 2; p++) {
        const int   q0 = base + 2 * p, q1 = q0 + 1;
        const float ax = Pb[q0 * 3 + 0], ay = Pb[q0 * 3 + 1], az = Pb[q0 * 3 + 2];
        const float bx = Pb[q1 * 3 + 0], by = Pb[q1 * 3 + 1], bz = Pb[q1 * 3 + 2];
        pxx[p]  = pack2(ax, bx);
        pyy[p]  = pack2(ay, by);
        pzz[p]  = pack2(az, bz);
        pp01[p] = pack2(ax * ax + ay * ay + az * az,
                        bx * bx + by * by + bz * bz);
    }

    float mn[QPT];
#pragma unroll
    for (int q = 0; q < QPT; q++) mn[q] = 3.4e38f;

    const ulonglong2* __restrict__ s2 = reinterpret_cast<const ulonglong2*>(sq);

    for (int j0 = 0; j0 < CHUNK; j0 += JT) {
        float m4[JT];
        // --- compute phase: JT columns ---
#pragma unroll
        for (int c = 0; c < JT; c++) {
            const int        j = j0 + c;
            const ulonglong2 a = s2[2 * j];       // {-2gx,-2gx, -2gy,-2gy}
            const ulonglong2 w = s2[2 * j + 1];   // {-2gz,-2gz,  gg,  gg }
            float t[QPT];
#pragma unroll
            for (int p = 0; p < QPT / 2; p++) {
                const ull s = fma2(pxx[p], a.x,
                                   fma2(pyy[p], a.y, fma2(pzz[p], w.x, w.y)));
                const ull v = add2(s, pp01[p]);       // full distance v1
                float lo, hi;
                unpack2(v, lo, hi);
                mn[2 * p]     = fminf(mn[2 * p], lo); // dir0 row-min on v1
                mn[2 * p + 1] = fminf(mn[2 * p + 1], hi);
                t[2 * p] = lo;
                t[2 * p + 1] = hi;
            }
            m4[c] = fminf(fminf(fminf(t[0], t[1]), fminf(t[2], t[3])),
                          fminf(fminf(t[4], t[5]), fminf(t[6], t[7])));
        }
        // --- truncated butterfly: 3 interleaved stages (xor 16, 8, 4) ---
#pragma unroll
        for (int st = 16; st >= 4; st >>= 1) {
#pragma unroll
            for (int c = 0; c < JT; c++)
                m4[c] = fminf(m4[c], __shfl_xor_sync(0xffffffffu, m4[c], st));
        }
        // lanes 0-3 each store their class row for these 4 columns (STS.128)
        if (lane < NCLS)
            *reinterpret_cast<float4*>(&colmin[wid][lane][j0]) =
                make_float4(m4[0], m4[1], m4[2], m4[3]);
    }

    // dir0 partials out (full distances), vectorized as 2x STG.128
    const size_t o0 = ((size_t)(b * GSPLIT + blockIdx.y)) * NN + base;
    *reinterpret_cast<float4*>(&g_part0[o0]) =
        make_float4(mn[0], mn[1], mn[2], mn[3]);
    *reinterpret_cast<float4*>(&g_part0[o0 + 4]) =
        make_float4(mn[4], mn[5], mn[6], mn[7]);

    __syncthreads();

    // dir1 epilogue: combine NWARP x NCLS partial mins per column
    for (int j = tid; j < CHUNK; j += TPB) {
        float m = colmin[0][0][j];
#pragma unroll
        for (int w = 0; w < NWARP; w++)
#pragma unroll
            for (int c = 0; c < NCLS; c++)
                m = fminf(m, colmin[w][c][j]);
        g_part1[((size_t)(b * XT + blockIdx.x)) * NN + coff + j] = m;
    }
}

// Final reduce: dir0 = min over chunks ; dir1 = min over query tiles.
// result = sum(all dists) / (B*N)   (N == M, forward_weight = 1)
#define TPB_RED 256
__global__ __launch_bounds__(TPB_RED) void chamfer_reduce_kernel(
    float* __restrict__ out) {
    __shared__ float red[TPB_RED];

    const int tid  = threadIdx.x;
    const int gidx = blockIdx.x * TPB_RED + tid;     // 0 .. 2*B*N-1

    float val;
    if (gidx < BB * NN) {                        // dir0 (pred -> gt)
        const int b = gidx / NN, q = gidx % NN;
        float m = 3.4e38f;
#pragma unroll
        for (int c = 0; c < GSPLIT; c++)
            m = fminf(m, g_part0[((size_t)(b * GSPLIT + c)) * NN + q]);
        val = m;
    } else {                                     // dir1 (gt -> pred)
        const int r = gidx - BB * NN;
        const int b = r / NN, j = r % NN;
        float m = 3.4e38f;
#pragma unroll
        for (int x = 0; x < XT; x++)
            m = fminf(m, g_part1[((size_t)(b * XT + x)) * NN + j]);
        val = m;
    }

    red[tid] = val;
    __syncthreads();
#pragma unroll
    for (int s = TPB_RED / 2; s > 0; s >>= 1) {
        if (tid < s) red[tid] += red[tid + s];
        __syncthreads();
    }
    if (tid == 0)
        atomicAdd(out, red[0] * (1.0f / ((float)BB * (float)NN)));
}

extern "C" void kernel_launch(void* const* d_in, const int* in_sizes, int n_in,
                              void* d_out, int out_size) {
    const float* pred = (const float*)d_in[0];
    const float* gt   = (const float*)d_in[1];
    float*       out  = (float*)d_out;

    dim3 grid(XT, GSPLIT, BB);   // 8 x 32 x 4 = 1024 blocks, single wave
    chamfer_fused_kernel<<<grid, TPB>>>(pred, gt, out);

    chamfer_reduce_kernel<<<(2 * BB * NN) / TPB_RED, TPB_RED>>>(out);
}